// round 14
// baseline (speedup 1.0000x reference)
#include <cuda_runtime.h>
#include <cuda_bf16.h>

#define NBINS   256
#define LOG_HW  20                 // pixels per image = 1<<20
#define HW      (1 << LOG_HW)
#define MAXIMG  64
#define BPI     64                 // hist blocks per image
#define CH4     (HW / 4 / BPI)     // 4096 float4 per hist block
#define API     128                // apply blocks per image
#define AP4     (HW / 4 / API)     // 2048 float4 per apply block (32 KB)
#define GRP     (BPI + API)        // 192 bids per group
#define LAG     8                  // apply trails hist by LAG images
#define NMM     1184               // minmax bids (first in grid)

// ------- scratch: zero/identity at module load; self-resetting each call ----
__device__ unsigned g_min_u = 0xFFFFFFFFu;      // +inf key
__device__ unsigned g_max_u = 0u;               // -inf key
__device__ unsigned g_mm_done = 0u;
__device__ unsigned long long g_mm_bits;        // (bits(mx)<<32)|bits(mn)
__device__ unsigned g_mm_ready = 0u;            // publish flag; reader-reset
__device__ unsigned g_mm_readers = 0u;          // hist blocks that consumed mm
__device__ unsigned g_hist[MAXIMG * NBINS];     // zero-init; otsu block resets
__device__ unsigned g_done[MAXIMG];             // zero-init; otsu block resets
__device__ unsigned g_applied[MAXIMG];          // zero-init; last reader resets
__device__ unsigned long long g_thr_pack[MAXIMG]; // (thr<<32)|ready; reader resets

__device__ __forceinline__ unsigned enc_f(float f) {
    unsigned u = __float_as_uint(f);
    return (u & 0x80000000u) ? ~u : (u | 0x80000000u);
}
__device__ __forceinline__ float dec_f(unsigned k) {
    return (k & 0x80000000u) ? __uint_as_float(k ^ 0x80000000u)
                             : __uint_as_float(~k);
}

__device__ __forceinline__ void mm4(float4 v, float& mn, float& mx) {
    mn = fminf(mn, fminf(fminf(v.x, v.y), fminf(v.z, v.w)));
    mx = fmaxf(mx, fmaxf(fmaxf(v.x, v.y), fmaxf(v.z, v.w)));
}

// ---- helper: bin 4 pixels into this warp's smem histogram copy -------------
__device__ __forceinline__ void hist4(float4 v, float mn, float scale,
                                      unsigned* mysh) {
    int i0 = (int)floorf(__fmul_rn(__fsub_rn(v.x, mn), scale));
    int i1 = (int)floorf(__fmul_rn(__fsub_rn(v.y, mn), scale));
    int i2 = (int)floorf(__fmul_rn(__fsub_rn(v.z, mn), scale));
    int i3 = (int)floorf(__fmul_rn(__fsub_rn(v.w, mn), scale));
    i0 = min(max(i0, 0), 255); i1 = min(max(i1, 0), 255);
    i2 = min(max(i2, 0), 255); i3 = min(max(i3, 0), 255);
    atomicAdd(&mysh[i0], 1u);
    atomicAdd(&mysh[i1], 1u);
    atomicAdd(&mysh[i2], 1u);
    atomicAdd(&mysh[i3], 1u);
}

// ======= single kernel: minmax bids, then per-group hist(+Otsu)/apply ========
// bids [0, NMM): minmax (wait on nothing; last publishes g_mm_bits+ready).
// bids >= NMM: group g, slot j. j<64: hist of image g (spins on mm_ready).
//              j>=64: apply of image g-LAG (spins on thr ready).
// Every wait targets strictly lower bids => deadlock-free under FIFO dispatch.
__global__ void __launch_bounds__(256) k_all(const float4* __restrict__ x4,
                                             float4* __restrict__ out4,
                                             float* __restrict__ out_thr,
                                             int n, long long n4) {
    int t = threadIdx.x;
    int b = blockIdx.x;

    if (b < NMM) {
        // ================= minmax path =====================================
        float mn = __int_as_float(0x7f800000);   // +inf
        float mx = __int_as_float(0xff800000);   // -inf
        unsigned rb = NMM - 1 - b;
        long long i = (long long)rb * 256 + t;
        long long stride = (long long)NMM * 256;
        for (; i + 7 * stride < n4; i += 8 * stride) {
            float4 a = x4[i];
            float4 bb = x4[i + stride];
            float4 c = x4[i + 2 * stride];
            float4 d = x4[i + 3 * stride];
            float4 e = x4[i + 4 * stride];
            float4 f = x4[i + 5 * stride];
            float4 g = x4[i + 6 * stride];
            float4 h = x4[i + 7 * stride];
            mm4(a, mn, mx); mm4(bb, mn, mx); mm4(c, mn, mx); mm4(d, mn, mx);
            mm4(e, mn, mx); mm4(f, mn, mx); mm4(g, mn, mx); mm4(h, mn, mx);
        }
        for (; i < n4; i += stride) {
            float4 v = x4[i];
            mm4(v, mn, mx);
        }
        #pragma unroll
        for (int o = 16; o; o >>= 1) {
            mn = fminf(mn, __shfl_down_sync(0xFFFFFFFFu, mn, o));
            mx = fmaxf(mx, __shfl_down_sync(0xFFFFFFFFu, mx, o));
        }
        __shared__ float smn[8], smx[8];
        int wid = t >> 5, lane = t & 31;
        if (lane == 0) { smn[wid] = mn; smx[wid] = mx; }
        __syncthreads();
        if (t == 0) {
            #pragma unroll
            for (int w = 1; w < 8; ++w) {
                mn = fminf(mn, smn[w]);
                mx = fmaxf(mx, smx[w]);
            }
            atomicMin(&g_min_u, enc_f(mn));
            atomicMax(&g_max_u, enc_f(mx));
            __threadfence();
            unsigned c = atomicAdd(&g_mm_done, 1u);
            if (c == NMM - 1) {              // last: publish + self-reset keys
                __threadfence();
                float fmn = dec_f(*(volatile unsigned*)&g_min_u);
                float fmx = dec_f(*(volatile unsigned*)&g_max_u);
                *(volatile unsigned long long*)&g_mm_bits =
                    ((unsigned long long)__float_as_uint(fmx) << 32)
                    | __float_as_uint(fmn);
                *(volatile unsigned*)&g_min_u   = 0xFFFFFFFFu;
                *(volatile unsigned*)&g_max_u   = 0u;
                *(volatile unsigned*)&g_mm_done = 0u;
                __threadfence();
                *(volatile unsigned*)&g_mm_ready = 1u;   // release
            }
        }
        return;
    }

    int wb = b - NMM;
    int g = wb / GRP;
    int j = wb - g * GRP;

    if (j >= BPI) {
        // ================= apply path ======================================
        int img = g - LAG;
        if (img < 0 || img >= n) return;    // filler block
        long long base = ((long long)img << (LOG_HW - 2))
                       + (long long)(j - BPI) * AP4;
        __shared__ float s_thr;
        if (t == 0) {
            unsigned long long pk;
            while (!((pk = *(volatile unsigned long long*)&g_thr_pack[img]) & 1ull))
                __nanosleep(32);
            s_thr = __uint_as_float((unsigned)(pk >> 32));
            unsigned c = atomicAdd(&g_applied[img], 1u);
            if (c == API - 1) {                  // last reader: self-reset
                *(volatile unsigned long long*)&g_thr_pack[img] = 0ull;
                *(volatile unsigned*)&g_applied[img] = 0u;
            }
        }
        __syncthreads();
        float thr = s_thr;
        const float4* p = x4 + base;
        float4* o = out4 + base;
        float4 v[8];
        #pragma unroll
        for (int k = 0; k < 8; ++k) v[k] = __ldcs(&p[k * 256 + t]);
        #pragma unroll
        for (int k = 0; k < 8; ++k) {
            v[k].x = (v[k].x <= thr) ? 0.0f : v[k].x;
            v[k].y = (v[k].y <= thr) ? 0.0f : v[k].y;
            v[k].z = (v[k].z <= thr) ? 0.0f : v[k].z;
            v[k].w = (v[k].w <= thr) ? 0.0f : v[k].w;
        }
        #pragma unroll
        for (int k = 0; k < 8; ++k) __stcs(&o[k * 256 + t], v[k]);
        return;
    }

    // ================= hist path ===========================================
    int img = g;
    if (img >= n) return;                    // filler block
    __shared__ unsigned sh[8 * NBINS];
    __shared__ unsigned long long s_mm;
    for (int i = t; i < 8 * NBINS; i += 256) sh[i] = 0u;

    if (t == 0) {                            // wait for global min/max
        while (!*(volatile unsigned*)&g_mm_ready) __nanosleep(32);
        __threadfence();                     // acquire
        s_mm = *(volatile unsigned long long*)&g_mm_bits;
    }
    __syncthreads();
    unsigned long long mmb = s_mm;
    float mn = __uint_as_float((unsigned)(mmb & 0xFFFFFFFFu));
    float mx = __uint_as_float((unsigned)(mmb >> 32));
    float scale = __fdiv_rn(256.0f, __fsub_rn(mx, mn));  // match ref fp32

    // mm consumption accounting: exactly n*BPI hist blocks; last resets flag
    if (t == 0) {
        unsigned c = atomicAdd(&g_mm_readers, 1u);
        if (c == (unsigned)(n * BPI) - 1u) {
            *(volatile unsigned*)&g_mm_ready   = 0u;
            *(volatile unsigned*)&g_mm_readers = 0u;
        }
    }

    const float4* p = x4 + ((long long)img << (LOG_HW - 2))
                         + ((long long)j * CH4);
    unsigned* mysh = &sh[(t >> 5) << 8];

    #pragma unroll
    for (int jj = 0; jj < CH4 / (256 * 8); ++jj) {       // 2 iterations, MLP=8
        int base = jj * 2048 + t;
        float4 r0 = p[base];
        float4 r1 = p[base + 256];
        float4 r2 = p[base + 512];
        float4 r3 = p[base + 768];
        float4 r4 = p[base + 1024];
        float4 r5 = p[base + 1280];
        float4 r6 = p[base + 1536];
        float4 r7 = p[base + 1792];
        hist4(r0, mn, scale, mysh);
        hist4(r1, mn, scale, mysh);
        hist4(r2, mn, scale, mysh);
        hist4(r3, mn, scale, mysh);
        hist4(r4, mn, scale, mysh);
        hist4(r5, mn, scale, mysh);
        hist4(r6, mn, scale, mysh);
        hist4(r7, mn, scale, mysh);
    }
    __syncthreads();

    unsigned s = sh[t] + sh[256 + t] + sh[512 + t] + sh[768 + t]
               + sh[1024 + t] + sh[1280 + t] + sh[1536 + t] + sh[1792 + t];
    if (s) atomicAdd(&g_hist[img * NBINS + t], s);

    // ---- non-blocking last-block-done -> Otsu inline
    __threadfence();
    __syncthreads();
    __shared__ unsigned s_last;
    if (t == 0) s_last = atomicAdd(&g_done[img], 1u);
    __syncthreads();
    if (s_last != BPI - 1) return;         // uniform across block
    __threadfence();                       // acquire peers' hist atomics

    __shared__ float P[NBINS];
    __shared__ float W[NBINS];
    __shared__ float S[NBINS];
    __shared__ unsigned long long s_key[8];

    P[t] = __fmul_rn((float)g_hist[img * NBINS + t],
                     9.5367431640625e-07f);          // * 2^-20, exact
    g_hist[img * NBINS + t] = 0u;                    // self-reset
    if (t == 0) g_done[img] = 0u;                    // self-reset
    __syncthreads();

    if (t == 0) {                          // fp32 cumsum, reference order
        float w = 0.0f, sm = 0.0f;
        #pragma unroll
        for (int i = 0; i < NBINS; i += 4) {
            float4 a = *(const float4*)&P[i];
            w = __fadd_rn(w, a.x); sm = __fadd_rn(sm, __fmul_rn(a.x, (float)(i + 0))); W[i + 0] = w; S[i + 0] = sm;
            w = __fadd_rn(w, a.y); sm = __fadd_rn(sm, __fmul_rn(a.y, (float)(i + 1))); W[i + 1] = w; S[i + 1] = sm;
            w = __fadd_rn(w, a.z); sm = __fadd_rn(sm, __fmul_rn(a.z, (float)(i + 2))); W[i + 2] = w; S[i + 2] = sm;
            w = __fadd_rn(w, a.w); sm = __fadd_rn(sm, __fmul_rn(a.w, (float)(i + 3))); W[i + 3] = w; S[i + 3] = sm;
        }
    }
    __syncthreads();

    float total = S[NBINS - 1];
    float wb2 = W[t];
    float wf = __fsub_rn(1.0f, wb2);
    float sb = S[t];
    float sf = __fsub_rn(total, sb);
    bool valid = (wb2 > 0.0f) && (wf > 0.0f);
    float mb = __fdiv_rn(sb, (wb2 > 0.0f) ? wb2 : 1.0f);
    float mf = __fdiv_rn(sf, (wf > 0.0f) ? wf : 1.0f);
    float d  = __fsub_rn(mb, mf);
    float iv = valid ? __fmul_rn(__fmul_rn(wb2, wf), __fmul_rn(d, d))
                     : __int_as_float(0xff800000);
    int anyv = __syncthreads_or(valid ? 1 : 0);

    unsigned long long key =               // first-max tie-break
        ((unsigned long long)enc_f(iv) << 32) | (unsigned)(NBINS - 1 - t);
    #pragma unroll
    for (int o = 16; o; o >>= 1) {
        unsigned long long other = __shfl_down_sync(0xFFFFFFFFu, key, o);
        if (other > key) key = other;
    }
    if ((t & 31) == 0) s_key[t >> 5] = key;
    __syncthreads();

    if (t == 0) {
        unsigned long long best = s_key[0];
        #pragma unroll
        for (int w = 1; w < 8; ++w)
            if (s_key[w] > best) best = s_key[w];
        int bt = NBINS - 1 - (int)(best & 0xFFFFFFFFu);
        int k = min(bt + 1, NBINS - 1);
        float delta = __fdiv_rn(__fsub_rn(mx, mn), (float)(NBINS - 1));
        float thr = anyv ? __fadd_rn(mn, __fmul_rn((float)k, delta)) : 0.0f;
        out_thr[img] = thr;
        *(volatile unsigned long long*)&g_thr_pack[img] =
            ((unsigned long long)__float_as_uint(thr) << 32) | 1ull;
    }
}

// ---------------- launch -----------------------------------------------------
extern "C" void kernel_launch(void* const* d_in, const int* in_sizes, int n_in,
                              void* d_out, int out_size) {
    const float* x = (const float*)d_in[0];
    long long npx = (long long)in_sizes[0];      // 48 * 2^20
    int n = (int)(npx >> LOG_HW);                // images
    long long n4 = npx >> 2;
    float* out = (float*)d_out;

    int grid = NMM + (n + LAG) * GRP;            // 1184 + 10752
    k_all<<<grid, 256>>>((const float4*)x, (float4*)out, out + npx, n, n4);
}

// round 15
// speedup vs baseline: 1.0868x; 1.0868x over previous
#include <cuda_runtime.h>
#include <cuda_bf16.h>

#define NBINS   256
#define LOG_HW  20                 // pixels per image = 1<<20
#define HW      (1 << LOG_HW)
#define MAXIMG  64
#define BPI     64                 // hist blocks per image
#define CH4     (HW / 4 / BPI)     // 4096 float4 per hist block
#define API     128                // apply blocks per image
#define AP4     (HW / 4 / API)     // 2048 float4 per apply block (32 KB)
#define GRP     (BPI + API)        // 192 bids per group
#define LAG     8                  // apply trails hist by LAG images
#define NMM     1184               // minmax grid

// ------- scratch: zero/identity at module load; self-resetting each call ----
__device__ unsigned g_min_u = 0xFFFFFFFFu;      // +inf key
__device__ unsigned g_max_u = 0u;               // -inf key
__device__ unsigned g_mm_done = 0u;
__device__ float2   g_mm;                       // final (mn, mx)
__device__ unsigned g_hist[MAXIMG * NBINS];     // zero-init; otsu block resets
__device__ unsigned g_done[MAXIMG];             // zero-init; otsu block resets
__device__ unsigned g_applied[MAXIMG];          // zero-init; last reader resets
__device__ unsigned long long g_thr_pack[MAXIMG]; // (thr<<32)|ready; reader resets

__device__ __forceinline__ unsigned enc_f(float f) {
    unsigned u = __float_as_uint(f);
    return (u & 0x80000000u) ? ~u : (u | 0x80000000u);
}
__device__ __forceinline__ float dec_f(unsigned k) {
    return (k & 0x80000000u) ? __uint_as_float(k ^ 0x80000000u)
                             : __uint_as_float(~k);
}

__device__ __forceinline__ void mm4(float4 v, float& mn, float& mx) {
    mn = fminf(mn, fminf(fminf(v.x, v.y), fminf(v.z, v.w)));
    mx = fmaxf(mx, fmaxf(fmaxf(v.x, v.y), fmaxf(v.z, v.w)));
}

// -------- K1: global min/max, DESCENDING sweep (leaves low images L2-warm) ---
// Rows of 256 float4; block b handles rows {R-1-b-k*NMM}. Per-warp access is
// contiguous 128B; collectively the sweep walks high->low addresses, so the
// ~126MB last touched at the end are the LOWEST addresses = images 0..30,
// exactly what k_work's hist phase reads first. Also starts at high addresses,
// which the previous replay's k_work tail left warm.
__global__ void __launch_bounds__(256) k_minmax(const float4* __restrict__ x,
                                                long long n4) {
    float mn = __int_as_float(0x7f800000);   // +inf
    float mx = __int_as_float(0xff800000);   // -inf
    long long R = n4 >> 8;                   // rows of 256 float4 (exact)
    int t = threadIdx.x;
    long long r = blockIdx.x;
    const long long BS = NMM;
    for (; r + 7 * BS < R; r += 8 * BS) {
        float4 a = x[(R - 1 - r) * 256 + t];
        float4 b = x[(R - 1 - (r + BS)) * 256 + t];
        float4 c = x[(R - 1 - (r + 2 * BS)) * 256 + t];
        float4 d = x[(R - 1 - (r + 3 * BS)) * 256 + t];
        float4 e = x[(R - 1 - (r + 4 * BS)) * 256 + t];
        float4 f = x[(R - 1 - (r + 5 * BS)) * 256 + t];
        float4 g = x[(R - 1 - (r + 6 * BS)) * 256 + t];
        float4 h = x[(R - 1 - (r + 7 * BS)) * 256 + t];
        mm4(a, mn, mx); mm4(b, mn, mx); mm4(c, mn, mx); mm4(d, mn, mx);
        mm4(e, mn, mx); mm4(f, mn, mx); mm4(g, mn, mx); mm4(h, mn, mx);
    }
    for (; r < R; r += BS) {
        float4 v = x[(R - 1 - r) * 256 + t];
        mm4(v, mn, mx);
    }
    #pragma unroll
    for (int o = 16; o; o >>= 1) {
        mn = fminf(mn, __shfl_down_sync(0xFFFFFFFFu, mn, o));
        mx = fmaxf(mx, __shfl_down_sync(0xFFFFFFFFu, mx, o));
    }
    __shared__ float smn[8], smx[8];
    int wid = t >> 5, lane = t & 31;
    if (lane == 0) { smn[wid] = mn; smx[wid] = mx; }
    __syncthreads();
    if (t == 0) {
        #pragma unroll
        for (int w = 1; w < 8; ++w) {
            mn = fminf(mn, smn[w]);
            mx = fmaxf(mx, smx[w]);
        }
        atomicMin(&g_min_u, enc_f(mn));
        atomicMax(&g_max_u, enc_f(mx));
        __threadfence();
        unsigned c = atomicAdd(&g_mm_done, 1u);
        if (c == gridDim.x - 1) {            // last block: snapshot + self-reset
            __threadfence();
            float fmn = dec_f(*(volatile unsigned*)&g_min_u);
            float fmx = dec_f(*(volatile unsigned*)&g_max_u);
            g_mm = make_float2(fmn, fmx);
            *(volatile unsigned*)&g_min_u   = 0xFFFFFFFFu;
            *(volatile unsigned*)&g_max_u   = 0u;
            *(volatile unsigned*)&g_mm_done = 0u;
        }
    }
}

// ---- helper: bin 4 pixels into this warp's smem histogram copy -------------
__device__ __forceinline__ void hist4(float4 v, float mn, float scale,
                                      unsigned* mysh) {
    int i0 = (int)floorf(__fmul_rn(__fsub_rn(v.x, mn), scale));
    int i1 = (int)floorf(__fmul_rn(__fsub_rn(v.y, mn), scale));
    int i2 = (int)floorf(__fmul_rn(__fsub_rn(v.z, mn), scale));
    int i3 = (int)floorf(__fmul_rn(__fsub_rn(v.w, mn), scale));
    i0 = min(max(i0, 0), 255); i1 = min(max(i1, 0), 255);
    i2 = min(max(i2, 0), 255); i3 = min(max(i3, 0), 255);
    atomicAdd(&mysh[i0], 1u);
    atomicAdd(&mysh[i1], 1u);
    atomicAdd(&mysh[i2], 1u);
    atomicAdd(&mysh[i3], 1u);
}

// ------ K2: pipelined interleave; apply trails hist by LAG images ------------
// Group g (bids g*192..g*192+191): first 64 = hist of image g (if g<n),
// next 128 = apply of image g-LAG (if >=0). Hist(i) fully dispatched+retired
// ~1.3 waves before apply(i) becomes resident -> near-zero spin, L2-warm reads.
__global__ void __launch_bounds__(256) k_work(const float* __restrict__ x,
                                              float4* __restrict__ out4,
                                              float* __restrict__ out_thr,
                                              int n) {
    int t = threadIdx.x;
    int g = blockIdx.x / GRP;
    int j = blockIdx.x - g * GRP;

    if (j >= BPI) {
        // ================= apply path ======================================
        int img = g - LAG;
        if (img < 0 || img >= n) return;    // filler block
        long long base = ((long long)img << (LOG_HW - 2))
                       + (long long)(j - BPI) * AP4;
        __shared__ float s_thr;
        if (t == 0) {
            unsigned long long pk;
            while (!((pk = *(volatile unsigned long long*)&g_thr_pack[img]) & 1ull))
                __nanosleep(32);
            s_thr = __uint_as_float((unsigned)(pk >> 32));
            unsigned c = atomicAdd(&g_applied[img], 1u);
            if (c == API - 1) {                  // last reader: self-reset
                *(volatile unsigned long long*)&g_thr_pack[img] = 0ull;
                *(volatile unsigned*)&g_applied[img] = 0u;
            }
        }
        __syncthreads();
        float thr = s_thr;
        const float4* p = (const float4*)x + base;
        float4* o = out4 + base;
        float4 v[8];
        #pragma unroll
        for (int k = 0; k < 8; ++k) v[k] = __ldcs(&p[k * 256 + t]);
        #pragma unroll
        for (int k = 0; k < 8; ++k) {
            v[k].x = (v[k].x <= thr) ? 0.0f : v[k].x;
            v[k].y = (v[k].y <= thr) ? 0.0f : v[k].y;
            v[k].z = (v[k].z <= thr) ? 0.0f : v[k].z;
            v[k].w = (v[k].w <= thr) ? 0.0f : v[k].w;
        }
        #pragma unroll
        for (int k = 0; k < 8; ++k) __stcs(&o[k * 256 + t], v[k]);
        return;
    }

    // ================= hist path ===========================================
    int img = g;
    if (img >= n) return;                    // filler block
    __shared__ unsigned sh[8 * NBINS];
    for (int i = t; i < 8 * NBINS; i += 256) sh[i] = 0u;

    float2 mm = g_mm;
    float mn = mm.x, mx = mm.y;
    float scale = __fdiv_rn(256.0f, __fsub_rn(mx, mn));  // match ref fp32
    __syncthreads();

    const float4* p = (const float4*)x + ((long long)img << (LOG_HW - 2))
                                       + ((long long)j * CH4);
    unsigned* mysh = &sh[(t >> 5) << 8];

    #pragma unroll
    for (int jj = 0; jj < CH4 / (256 * 8); ++jj) {       // 2 iterations, MLP=8
        int base = jj * 2048 + t;
        float4 r0 = p[base];
        float4 r1 = p[base + 256];
        float4 r2 = p[base + 512];
        float4 r3 = p[base + 768];
        float4 r4 = p[base + 1024];
        float4 r5 = p[base + 1280];
        float4 r6 = p[base + 1536];
        float4 r7 = p[base + 1792];
        hist4(r0, mn, scale, mysh);
        hist4(r1, mn, scale, mysh);
        hist4(r2, mn, scale, mysh);
        hist4(r3, mn, scale, mysh);
        hist4(r4, mn, scale, mysh);
        hist4(r5, mn, scale, mysh);
        hist4(r6, mn, scale, mysh);
        hist4(r7, mn, scale, mysh);
    }
    __syncthreads();

    unsigned s = sh[t] + sh[256 + t] + sh[512 + t] + sh[768 + t]
               + sh[1024 + t] + sh[1280 + t] + sh[1536 + t] + sh[1792 + t];
    if (s) atomicAdd(&g_hist[img * NBINS + t], s);

    // ---- non-blocking last-block-done -> Otsu inline
    __threadfence();
    __syncthreads();
    __shared__ unsigned s_last;
    if (t == 0) s_last = atomicAdd(&g_done[img], 1u);
    __syncthreads();
    if (s_last != BPI - 1) return;         // uniform across block
    __threadfence();                       // acquire peers' hist atomics

    __shared__ float P[NBINS];
    __shared__ float W[NBINS];
    __shared__ float S[NBINS];
    __shared__ unsigned long long s_key[8];

    P[t] = __fmul_rn((float)g_hist[img * NBINS + t],
                     9.5367431640625e-07f);          // * 2^-20, exact
    g_hist[img * NBINS + t] = 0u;                    // self-reset
    if (t == 0) g_done[img] = 0u;                    // self-reset
    __syncthreads();

    if (t == 0) {                          // fp32 cumsum, reference order
        float w = 0.0f, sm = 0.0f;
        #pragma unroll
        for (int i = 0; i < NBINS; i += 4) {
            float4 a = *(const float4*)&P[i];
            w = __fadd_rn(w, a.x); sm = __fadd_rn(sm, __fmul_rn(a.x, (float)(i + 0))); W[i + 0] = w; S[i + 0] = sm;
            w = __fadd_rn(w, a.y); sm = __fadd_rn(sm, __fmul_rn(a.y, (float)(i + 1))); W[i + 1] = w; S[i + 1] = sm;
            w = __fadd_rn(w, a.z); sm = __fadd_rn(sm, __fmul_rn(a.z, (float)(i + 2))); W[i + 2] = w; S[i + 2] = sm;
            w = __fadd_rn(w, a.w); sm = __fadd_rn(sm, __fmul_rn(a.w, (float)(i + 3))); W[i + 3] = w; S[i + 3] = sm;
        }
    }
    __syncthreads();

    float total = S[NBINS - 1];
    float wb = W[t];
    float wf = __fsub_rn(1.0f, wb);
    float sb = S[t];
    float sf = __fsub_rn(total, sb);
    bool valid = (wb > 0.0f) && (wf > 0.0f);
    float mb = __fdiv_rn(sb, (wb > 0.0f) ? wb : 1.0f);
    float mf = __fdiv_rn(sf, (wf > 0.0f) ? wf : 1.0f);
    float d  = __fsub_rn(mb, mf);
    float iv = valid ? __fmul_rn(__fmul_rn(wb, wf), __fmul_rn(d, d))
                     : __int_as_float(0xff800000);
    int anyv = __syncthreads_or(valid ? 1 : 0);

    unsigned long long key =               // first-max tie-break
        ((unsigned long long)enc_f(iv) << 32) | (unsigned)(NBINS - 1 - t);
    #pragma unroll
    for (int o = 16; o; o >>= 1) {
        unsigned long long other = __shfl_down_sync(0xFFFFFFFFu, key, o);
        if (other > key) key = other;
    }
    if ((t & 31) == 0) s_key[t >> 5] = key;
    __syncthreads();

    if (t == 0) {
        unsigned long long best = s_key[0];
        #pragma unroll
        for (int w = 1; w < 8; ++w)
            if (s_key[w] > best) best = s_key[w];
        int bt = NBINS - 1 - (int)(best & 0xFFFFFFFFu);
        int k = min(bt + 1, NBINS - 1);
        float delta = __fdiv_rn(__fsub_rn(mx, mn), (float)(NBINS - 1));
        float thr = anyv ? __fadd_rn(mn, __fmul_rn((float)k, delta)) : 0.0f;
        out_thr[img] = thr;
        *(volatile unsigned long long*)&g_thr_pack[img] =
            ((unsigned long long)__float_as_uint(thr) << 32) | 1ull;
    }
}

// ---------------- launch -----------------------------------------------------
extern "C" void kernel_launch(void* const* d_in, const int* in_sizes, int n_in,
                              void* d_out, int out_size) {
    const float* x = (const float*)d_in[0];
    long long npx = (long long)in_sizes[0];      // 48 * 2^20
    int n = (int)(npx >> LOG_HW);                // images
    long long n4 = npx >> 2;
    float* out = (float*)d_out;

    k_minmax<<<NMM, 256>>>((const float4*)x, n4);
    k_work  <<<(n + LAG) * GRP, 256>>>(x, (float4*)out, out + npx, n);
}